// round 3
// baseline (speedup 1.0000x reference)
#include <cuda_runtime.h>
#include <math.h>

// Problem constants (fixed shapes for HoughSplitLoss_12884901888574)
#define B_   32
#define L_   6
#define A_   1024
#define R_   1024
#define NPTS (B_ * L_)            // 192
#define RAD  5
#define WIN  11                   // 2*RAD+1
#define NWIN (WIN * WIN)          // 121
#define NELEM (1024u * 1024u)     // per-batch plane elements
#define TOTAL_ELEMS ((long long)B_ * A_ * R_)  // 33554432
#define NBLK NPTS                 // 192 blocks, all co-resident (148 SMs)
#define NTHR 128

// Fixed-point scales for deterministic integer accumulation.
#define SCALE_MAIN 4194304.0      // 2^22
#define SCALE_FB   1048576.0      // 2^20

// Scratch globals. Zero at module load; the elected last block restores them
// to zero at the end of every launch, so each launch (correctness run + every
// graph replay) sees identical initial state -> deterministic.
__device__ unsigned long long g_acc;   // main-path fixed-point accumulator
__device__ unsigned int       g_cnt;   // main-phase arrival counter
__device__ volatile int       g_flag;  // 0=pending, 1=main wrote out, 2=fallback
__device__ unsigned long long g_facc;  // fallback accumulator
__device__ unsigned int       g_done;  // final arrival counter (reset electing)

__device__ __forceinline__ float sigmoidf_(float x) {
    return 1.0f / (1.0f + expf(-x));
}

// ---------------------------------------------------------------------------
// Single fused kernel. Phase A: one block per (batch,point), 121-cell gather,
// deterministic block reduce, fixed-point atomic merge; last block publishes
// total via g_flag. Phase B: all blocks spin on g_flag (all 192 blocks are
// resident in wave 1, so this cannot deadlock). Phase C (flag==2 only, i.e.
// total==0): same blocks grid-stride the full-plane fallback. Phase D: last
// block to finish writes the fallback result if needed and resets globals.
// ---------------------------------------------------------------------------
__global__ __launch_bounds__(NTHR)
void loss_fused(const float* __restrict__ pre_hough,
                const float* __restrict__ gt_hough,
                const int*   __restrict__ in_pre_points,
                const int*   __restrict__ gt_points,
                float*       __restrict__ out)
{
    __shared__ int   sX, sY;
    __shared__ float sW;
    __shared__ float s_part[4];
    __shared__ int   s_flag;
    __shared__ double s_red[NTHR];

    const int p   = blockIdx.x;     // 0..191
    const int b   = p / L_;
    const int l   = p - b * L_;
    const int tid = threadIdx.x;

    // ---- Phase A0: point prep (thread 0) ----
    if (tid == 0) {
        const int4* pp = (const int4*)(in_pre_points + b * (L_ * 2));
        const int4 v0 = pp[0], v1 = pp[1], v2 = pp[2];
        int px[L_] = { v0.x, v0.z, v1.x, v1.z, v2.x, v2.z };
        int py[L_] = { v0.y, v0.w, v1.y, v1.w, v2.y, v2.w };
        long long key[L_];
        #pragma unroll
        for (int i = 0; i < L_; ++i)
            key[i] = (px[i] < 0) ? (1LL << 30)
                                 : (long long)px[i] * 10000LL + (long long)py[i];
        // Stable insertion sort (matches stable argsort; ties outcome-neutral).
        #pragma unroll
        for (int i = 1; i < L_; ++i) {
            long long kk = key[i];
            int kx = px[i], ky = py[i];
            int j = i - 1;
            while (j >= 0 && key[j] > kk) {
                key[j + 1] = key[j]; px[j + 1] = px[j]; py[j + 1] = py[j];
                --j;
            }
            key[j + 1] = kk; px[j + 1] = kx; py[j + 1] = ky;
        }
        const int2 g = ((const int2*)(gt_points + b * (L_ * 2)))[l];
        const bool use_gt   = (g.x >= 0);
        const bool one_inv  = (px[l] < 0) || (g.x < 0);
        const bool both_inv = (px[l] < 0) && (g.x < 0);
        sX = use_gt ? g.x : px[l];
        sY = use_gt ? g.y : py[l];
        sW = both_inv ? 0.0f : (one_inv ? 10.0f : 1.0f) / (float)(RAD * RAD);
    }
    __syncthreads();

    // ---- Phase A1: one window cell per thread (121 of 128 active) ----
    float acc = 0.0f;
    if (tid < NWIN) {
        const int di = tid / WIN - RAD;
        const int dj = tid % WIN - RAD;
        const int xi = sX + di;
        const int yi = sY + dj;
        if (xi >= 0 && xi < R_ && yi >= 0 && yi < A_) {
            const size_t off = (size_t)b * NELEM + (size_t)xi * R_ + yi;
            acc = fabsf(sigmoidf_(pre_hough[off]) - gt_hough[off]);
        }
    }
    #pragma unroll
    for (int off = 16; off > 0; off >>= 1)
        acc += __shfl_down_sync(0xffffffffu, acc, off);
    if ((tid & 31) == 0) s_part[tid >> 5] = acc;
    __syncthreads();

    // ---- Phase A2: merge + publish (thread 0 of each block) ----
    if (tid == 0) {
        const float sum = (s_part[0] + s_part[1]) + (s_part[2] + s_part[3]);
        const long long q = __double2ll_rn((double)(sum * sW) * SCALE_MAIN);
        atomicAdd(&g_acc, (unsigned long long)q);
        __threadfence();
        const unsigned old = atomicAdd(&g_cnt, 1u);
        if (old == (unsigned)(NBLK - 1)) {
            const unsigned long long a = atomicAdd(&g_acc, 0ULL);
            const float total = (float)((double)a / SCALE_MAIN);
            if (total != 0.0f) {
                out[0] = total / (float)B_;
                __threadfence();
                g_flag = 1;
            } else {
                __threadfence();
                g_flag = 2;
            }
        }
    }

    // ---- Phase B: spin until total is decided (all blocks resident) ----
    if (tid == 0) {
        int f;
        while ((f = g_flag) == 0) { __nanosleep(40); }
        s_flag = f;
    }
    __syncthreads();

    // ---- Phase C: fallback (taken only when total == 0) ----
    if (s_flag == 2) {
        const long long stride = (long long)NBLK * NTHR;
        long long i = (long long)p * NTHR + tid;
        double d = 0.0;
        for (; i < TOTAL_ELEMS; i += stride)
            d += (double)fabsf(sigmoidf_(pre_hough[i]) - gt_hough[i]);
        s_red[tid] = d;
        __syncthreads();
        for (int off = NTHR / 2; off > 0; off >>= 1) {
            if (tid < off) s_red[tid] += s_red[tid + off];
            __syncthreads();
        }
        if (tid == 0) {
            const long long q = __double2ll_rn(s_red[0] * SCALE_FB);
            atomicAdd(&g_facc, (unsigned long long)q);
        }
    }

    // ---- Phase D: last block finalizes fallback (if any) and resets state ----
    if (tid == 0) {
        __threadfence();
        const unsigned old = atomicAdd(&g_done, 1u);
        if (old == (unsigned)(NBLK - 1)) {
            if (s_flag == 2) {
                const unsigned long long a = atomicAdd(&g_facc, 0ULL);
                out[0] = (float)(((double)a / SCALE_FB) / (double)TOTAL_ELEMS);
            }
            // Restore invariant for the next launch / graph replay.
            g_acc  = 0ULL;
            g_cnt  = 0u;
            g_facc = 0ULL;
            g_done = 0u;
            __threadfence();
            g_flag = 0;
        }
    }
}

// ---------------------------------------------------------------------------
extern "C" void kernel_launch(void* const* d_in, const int* in_sizes, int n_in,
                              void* d_out, int out_size)
{
    const float* pre_hough     = (const float*)d_in[0];
    const float* gt_hough      = (const float*)d_in[1];
    const int*   in_pre_points = (const int*)d_in[2];
    const int*   gt_points     = (const int*)d_in[3];
    float*       out           = (float*)d_out;

    loss_fused<<<NBLK, NTHR>>>(pre_hough, gt_hough, in_pre_points, gt_points, out);
}

// round 4
// speedup vs baseline: 1.2242x; 1.2242x over previous
#include <cuda_runtime.h>
#include <math.h>

// Problem constants (fixed shapes for HoughSplitLoss_12884901888574)
#define B_   32
#define L_   6
#define A_   1024
#define R_   1024
#define NPTS (B_ * L_)            // 192
#define RAD  5
#define WIN  11                   // 2*RAD+1
#define NWIN (WIN * WIN)          // 121
#define NELEM (1024u * 1024u)     // per-batch plane elements
#define TOTAL_ELEMS ((long long)B_ * A_ * R_)  // 33554432
#define NBLK NPTS                 // 192 blocks
#define NTHR 128

// Fixed-point scales for deterministic integer accumulation.
#define SCALE_MAIN 4194304.0      // 2^22

// Scratch globals. Zero at module load; the elected last block resets them
// immediately after reading (no other block touches them afterwards), so each
// launch / graph replay sees identical initial state -> deterministic.
__device__ unsigned long long g_acc;   // fixed-point total accumulator
__device__ unsigned int       g_cnt;   // block arrival counter

__device__ __forceinline__ float sigmoidf_(float x) {
    return 1.0f / (1.0f + expf(-x));
}

// ---------------------------------------------------------------------------
// Single kernel, no global barrier.
//   Phase A: one block per (batch, point). All 128 threads redundantly do the
//            point prep (broadcast loads + identical stable sort) so the
//            gather issues without a thread0->shared->sync serialization.
//            121-cell gather, deterministic block reduce, fixed-point atomic
//            merge into g_acc.
//   Phase B: the LAST-arriving block reads total, resets globals, and writes
//            out = total/B. Only if total == 0 (semantically required branch,
//            never taken on this data) does that single block compute the
//            full-plane fallback mean itself.
// ---------------------------------------------------------------------------
__global__ __launch_bounds__(NTHR)
void loss_fused(const float* __restrict__ pre_hough,
                const float* __restrict__ gt_hough,
                const int*   __restrict__ in_pre_points,
                const int*   __restrict__ gt_points,
                float*       __restrict__ out)
{
    __shared__ float s_part[4];
    __shared__ int   s_fb;          // 1 => this block must run the fallback
    __shared__ double s_red[NTHR];

    const int p   = blockIdx.x;     // 0..191
    const int b   = p / L_;
    const int l   = p - b * L_;
    const int tid = threadIdx.x;

    if (tid == 0) s_fb = 0;

    // ---- Phase A0: point prep, redundantly in every thread (broadcast) ----
    int X, Y;
    float W;
    {
        const int4* pp = (const int4*)(in_pre_points + b * (L_ * 2));
        const int4 v0 = pp[0], v1 = pp[1], v2 = pp[2];
        const int2 g  = ((const int2*)(gt_points + b * (L_ * 2)))[l];
        int px[L_] = { v0.x, v0.z, v1.x, v1.z, v2.x, v2.z };
        int py[L_] = { v0.y, v0.w, v1.y, v1.w, v2.y, v2.w };
        long long key[L_];
        #pragma unroll
        for (int i = 0; i < L_; ++i)
            key[i] = (px[i] < 0) ? (1LL << 30)
                                 : (long long)px[i] * 10000LL + (long long)py[i];
        // Stable insertion sort (matches stable argsort; ties outcome-neutral).
        #pragma unroll
        for (int i = 1; i < L_; ++i) {
            long long kk = key[i];
            int kx = px[i], ky = py[i];
            int j = i - 1;
            while (j >= 0 && key[j] > kk) {
                key[j + 1] = key[j]; px[j + 1] = px[j]; py[j + 1] = py[j];
                --j;
            }
            key[j + 1] = kk; px[j + 1] = kx; py[j + 1] = ky;
        }
        const bool use_gt   = (g.x >= 0);
        const bool one_inv  = (px[l] < 0) || (g.x < 0);
        const bool both_inv = (px[l] < 0) && (g.x < 0);
        X = use_gt ? g.x : px[l];
        Y = use_gt ? g.y : py[l];
        W = both_inv ? 0.0f : (one_inv ? 10.0f : 1.0f) / (float)(RAD * RAD);
    }

    // ---- Phase A1: one window cell per thread (121 of 128 active) ----
    float acc = 0.0f;
    if (tid < NWIN) {
        const int di = tid / WIN - RAD;
        const int dj = tid % WIN - RAD;
        const int xi = X + di;
        const int yi = Y + dj;
        if (xi >= 0 && xi < R_ && yi >= 0 && yi < A_) {
            const size_t off = (size_t)b * NELEM + (size_t)xi * R_ + yi;
            acc = fabsf(sigmoidf_(pre_hough[off]) - gt_hough[off]);
        }
    }
    #pragma unroll
    for (int off = 16; off > 0; off >>= 1)
        acc += __shfl_down_sync(0xffffffffu, acc, off);
    if ((tid & 31) == 0) s_part[tid >> 5] = acc;
    __syncthreads();

    // ---- Phase A2: merge; last-arriving block decides ----
    if (tid == 0) {
        const float sum = (s_part[0] + s_part[1]) + (s_part[2] + s_part[3]);
        const long long q = __double2ll_rn((double)(sum * W) * SCALE_MAIN);
        atomicAdd(&g_acc, (unsigned long long)q);
        __threadfence();
        const unsigned old = atomicAdd(&g_cnt, 1u);
        if (old == (unsigned)(NBLK - 1)) {
            const unsigned long long a = atomicAdd(&g_acc, 0ULL);
            // Reset invariant for next launch/replay (no other block reads these).
            g_acc = 0ULL;
            g_cnt = 0u;
            __threadfence();
            const float total = (float)((double)a / SCALE_MAIN);
            if (total != 0.0f) {
                out[0] = total / (float)B_;
            } else {
                s_fb = 1;   // this block alone runs the fallback
            }
        }
    }
    __syncthreads();

    // ---- Phase B: fallback, executed by ONE block only when total == 0.
    //      Never taken on this dataset; correctness-only path. ----
    if (s_fb) {
        double d = 0.0;
        for (long long i = tid; i < TOTAL_ELEMS; i += NTHR)
            d += (double)fabsf(sigmoidf_(pre_hough[i]) - gt_hough[i]);
        s_red[tid] = d;
        __syncthreads();
        for (int off = NTHR / 2; off > 0; off >>= 1) {
            if (tid < off) s_red[tid] += s_red[tid + off];
            __syncthreads();
        }
        if (tid == 0)
            out[0] = (float)(s_red[0] / (double)TOTAL_ELEMS);
    }
}

// ---------------------------------------------------------------------------
extern "C" void kernel_launch(void* const* d_in, const int* in_sizes, int n_in,
                              void* d_out, int out_size)
{
    const float* pre_hough     = (const float*)d_in[0];
    const float* gt_hough      = (const float*)d_in[1];
    const int*   in_pre_points = (const int*)d_in[2];
    const int*   gt_points     = (const int*)d_in[3];
    float*       out           = (float*)d_out;

    loss_fused<<<NBLK, NTHR>>>(pre_hough, gt_hough, in_pre_points, gt_points, out);
}

// round 5
// speedup vs baseline: 1.2647x; 1.0331x over previous
#include <cuda_runtime.h>
#include <math.h>

// Problem constants (fixed shapes for HoughSplitLoss_12884901888574)
#define B_   32
#define L_   6
#define A_   1024
#define R_   1024
#define NPTS (B_ * L_)            // 192
#define RAD  5
#define WIN  11                   // 2*RAD+1
#define NWIN (WIN * WIN)          // 121
#define NELEM (1024u * 1024u)     // per-batch plane elements
#define TOTAL_ELEMS ((long long)B_ * A_ * R_)  // 33554432

#define NTHR   256                // 8 warps/block, one point per warp
#define WARPS  (NTHR / 32)        // 8
#define NBLK   (NPTS / WARPS)     // 24 blocks

// Fixed-point scale for deterministic integer accumulation.
#define SCALE_MAIN 4194304.0      // 2^22

// Scratch globals. Zero at module load; the elected last block resets them
// immediately after reading, so every launch / graph replay sees identical
// initial state -> deterministic.
__device__ unsigned long long g_acc;   // fixed-point total accumulator
__device__ unsigned int       g_cnt;   // block arrival counter

__device__ __forceinline__ float sigmoidf_(float x) {
    // Fast sigmoid: |err| ~1e-7 relative, far inside the 1e-3 budget.
    return __frcp_rn(1.0f + __expf(-x));
}

// ---------------------------------------------------------------------------
// One warp per point; 24 blocks x 256 threads. Per-point sums are quantized
// to fixed point PER POINT (order-independent from there on), integer-summed
// within the block, and merged with ONE atomicAdd per block (24 same-address
// atomics total vs 192 before -> removes the L2 atomic serialization from the
// critical path). Last-arriving block writes out; the total==0 fallback
// branch (never taken on this data) is handled by that single block.
// ---------------------------------------------------------------------------
__global__ __launch_bounds__(NTHR)
void loss_fused(const float* __restrict__ pre_hough,
                const float* __restrict__ gt_hough,
                const int*   __restrict__ in_pre_points,
                const int*   __restrict__ gt_points,
                float*       __restrict__ out)
{
    __shared__ long long s_q[WARPS];
    __shared__ int       s_fb;      // 1 => this block runs the fallback
    __shared__ double    s_red[NTHR];

    const int tid  = threadIdx.x;
    const int warp = tid >> 5;
    const int lane = tid & 31;
    const int p    = blockIdx.x * WARPS + warp;   // 0..191
    const int b    = p / L_;
    const int l    = p - b * L_;

    if (tid == 0) s_fb = 0;

    // ---- Point prep, redundantly in every thread of the warp (broadcast) ----
    int X, Y;
    float W;
    {
        const int4* pp = (const int4*)(in_pre_points + b * (L_ * 2));
        const int4 v0 = pp[0], v1 = pp[1], v2 = pp[2];
        const int2 g  = ((const int2*)(gt_points + b * (L_ * 2)))[l];
        int px[L_] = { v0.x, v0.z, v1.x, v1.z, v2.x, v2.z };
        int py[L_] = { v0.y, v0.w, v1.y, v1.w, v2.y, v2.w };
        long long key[L_];
        #pragma unroll
        for (int i = 0; i < L_; ++i)
            key[i] = (px[i] < 0) ? (1LL << 30)
                                 : (long long)px[i] * 10000LL + (long long)py[i];
        // Stable insertion sort (matches stable argsort; ties outcome-neutral).
        #pragma unroll
        for (int i = 1; i < L_; ++i) {
            long long kk = key[i];
            int kx = px[i], ky = py[i];
            int j = i - 1;
            while (j >= 0 && key[j] > kk) {
                key[j + 1] = key[j]; px[j + 1] = px[j]; py[j + 1] = py[j];
                --j;
            }
            key[j + 1] = kk; px[j + 1] = kx; py[j + 1] = ky;
        }
        const bool use_gt   = (g.x >= 0);
        const bool one_inv  = (px[l] < 0) || (g.x < 0);
        const bool both_inv = (px[l] < 0) && (g.x < 0);
        X = use_gt ? g.x : px[l];
        Y = use_gt ? g.y : py[l];
        W = both_inv ? 0.0f : (one_inv ? 10.0f : 1.0f) / (float)(RAD * RAD);
    }

    // ---- Gather: lane covers cells lane+32*it, it=0..3 (121 cells).
    //      All 4 LDG pairs are independent -> MLP=8 per thread. ----
    float vp[4], vg[4];
    #pragma unroll
    for (int it = 0; it < 4; ++it) {
        const int idx = lane + it * 32;
        const int di  = idx / WIN - RAD;
        const int dj  = idx % WIN - RAD;
        const int xi  = X + di;
        const int yi  = Y + dj;
        const bool ok = (idx < NWIN) & (xi >= 0) & (xi < R_) & (yi >= 0) & (yi < A_);
        const size_t off = (size_t)b * NELEM + (size_t)(ok ? xi : 0) * R_ + (ok ? yi : 0);
        vp[it] = ok ? pre_hough[off] : 0.0f;
        vg[it] = ok ? gt_hough[off]  : 0.0f;
        if (!ok) { vp[it] = 0.0f; vg[it] = 0.0f; }
    }
    float acc = 0.0f;
    #pragma unroll
    for (int it = 0; it < 4; ++it) {
        const int idx = lane + it * 32;
        const int di  = idx / WIN - RAD;
        const int dj  = idx % WIN - RAD;
        const int xi  = X + di;
        const int yi  = Y + dj;
        const bool ok = (idx < NWIN) & (xi >= 0) & (xi < R_) & (yi >= 0) & (yi < A_);
        if (ok) acc += fabsf(sigmoidf_(vp[it]) - vg[it]);
    }

    // ---- Warp reduce (deterministic), quantize per point ----
    #pragma unroll
    for (int off = 16; off > 0; off >>= 1)
        acc += __shfl_down_sync(0xffffffffu, acc, off);
    if (lane == 0)
        s_q[warp] = __double2ll_rn((double)(acc * W) * SCALE_MAIN);
    __syncthreads();

    // ---- One atomic per block; last-arriving block decides ----
    if (tid == 0) {
        long long qs = 0;
        #pragma unroll
        for (int w = 0; w < WARPS; ++w) qs += s_q[w];
        atomicAdd(&g_acc, (unsigned long long)qs);
        __threadfence();
        const unsigned old = atomicAdd(&g_cnt, 1u);
        if (old == (unsigned)(NBLK - 1)) {
            const unsigned long long a = atomicAdd(&g_acc, 0ULL);
            g_acc = 0ULL;               // restore invariant for next replay
            g_cnt = 0u;
            __threadfence();
            const float total = (float)((double)a / SCALE_MAIN);
            if (total != 0.0f) {
                out[0] = total / (float)B_;
            } else {
                s_fb = 1;               // this block alone runs the fallback
            }
        }
    }
    __syncthreads();

    // ---- Fallback: ONE block, only when total == 0 (never on this data) ----
    if (s_fb) {
        double d = 0.0;
        for (long long i = tid; i < TOTAL_ELEMS; i += NTHR)
            d += (double)fabsf(1.0f / (1.0f + expf(-pre_hough[i])) - gt_hough[i]);
        s_red[tid] = d;
        __syncthreads();
        for (int off = NTHR / 2; off > 0; off >>= 1) {
            if (tid < off) s_red[tid] += s_red[tid + off];
            __syncthreads();
        }
        if (tid == 0)
            out[0] = (float)(s_red[0] / (double)TOTAL_ELEMS);
    }
}

// ---------------------------------------------------------------------------
extern "C" void kernel_launch(void* const* d_in, const int* in_sizes, int n_in,
                              void* d_out, int out_size)
{
    const float* pre_hough     = (const float*)d_in[0];
    const float* gt_hough      = (const float*)d_in[1];
    const int*   in_pre_points = (const int*)d_in[2];
    const int*   gt_points     = (const int*)d_in[3];
    float*       out           = (float*)d_out;

    loss_fused<<<NBLK, NTHR>>>(pre_hough, gt_hough, in_pre_points, gt_points, out);
}